// round 2
// baseline (speedup 1.0000x reference)
#include <cuda_runtime.h>

#define N_NODES 50000
#define N_EDGES 1600000
#define F 256
#define OUTF 64

// ---------------- scratch (static device globals; no runtime alloc) ----------
__device__ float g_h1[(long)N_NODES * F];    // layer-0 output
__device__ float g_agg[(long)N_NODES * F];   // neighbor-mean buffer (reused)
__device__ int   g_rowptr[N_NODES + 1];
__device__ int   g_cursor[N_NODES];
__device__ int   g_col[N_EDGES];
__device__ int   g_deg[N_NODES];
__device__ float g_invdeg[N_NODES];

// ---------------- CSR build ---------------------------------------------------
__global__ void count_kernel(const int* __restrict__ dst) {
    int e = blockIdx.x * blockDim.x + threadIdx.x;
    if (e < N_EDGES) atomicAdd(&g_deg[dst[e]], 1);
}

// single-block exclusive scan over 50000 degrees; also writes cursor + inv_deg
__global__ void scan_kernel() {
    __shared__ int sm[1024];
    __shared__ int carry_s;
    int tid = threadIdx.x;
    if (tid == 0) carry_s = 0;
    __syncthreads();
    for (int base = 0; base < N_NODES; base += 1024) {
        int idx = base + tid;
        int v = (idx < N_NODES) ? g_deg[idx] : 0;
        sm[tid] = v;
        __syncthreads();
        #pragma unroll
        for (int off = 1; off < 1024; off <<= 1) {
            int t = (tid >= off) ? sm[tid - off] : 0;
            __syncthreads();
            sm[tid] += t;
            __syncthreads();
        }
        int excl = carry_s + sm[tid] - v;
        if (idx < N_NODES) {
            g_rowptr[idx] = excl;
            g_cursor[idx] = excl;
            g_invdeg[idx] = 1.0f / (float)max(v, 1);
        }
        __syncthreads();
        if (tid == 1023) carry_s += sm[1023];
        __syncthreads();
    }
    if (tid == 0) g_rowptr[N_NODES] = carry_s;
}

__global__ void fill_kernel(const int* __restrict__ src, const int* __restrict__ dst) {
    int e = blockIdx.x * blockDim.x + threadIdx.x;
    if (e < N_EDGES) {
        int d = dst[e];
        int p = atomicAdd(&g_cursor[d], 1);
        g_col[p] = src[e];
    }
}

// ---------------- SpMM: out[n,:] = inv_deg[n] * sum_{e in row n} h[col[e],:] --
// one block per node, 256 threads = 256 feature lanes, cols staged in smem
__global__ __launch_bounds__(256) void spmm_kernel(const float* __restrict__ h,
                                                   float* __restrict__ out) {
    int n = blockIdx.x;
    int tid = threadIdx.x;
    int s = g_rowptr[n];
    int e = g_rowptr[n + 1];
    __shared__ int cols[256];
    float a0 = 0.f, a1 = 0.f, a2 = 0.f, a3 = 0.f;
    for (int base = s; base < e; base += 256) {
        int cnt = min(256, e - base);
        __syncthreads();
        if (tid < cnt) cols[tid] = g_col[base + tid];
        __syncthreads();
        int i = 0;
        for (; i + 4 <= cnt; i += 4) {
            a0 += h[cols[i + 0] * F + tid];
            a1 += h[cols[i + 1] * F + tid];
            a2 += h[cols[i + 2] * F + tid];
            a3 += h[cols[i + 3] * F + tid];
        }
        for (; i < cnt; i++) a0 += h[cols[i] * F + tid];
    }
    out[n * F + tid] = (a0 + a1 + a2 + a3) * g_invdeg[n];
}

// ---------------- fused dual-GEMM: C = relu?([A1|A2]@[W1;W2] + b) -------------
// BM=128, BN=64, BK=16, 256 threads, 8x4 micro-tile per thread, K=256 per half
#define BM 128
#define BN 64
#define BK 16

__global__ __launch_bounds__(256) void gemm_kernel(
    const float* __restrict__ A1, const float* __restrict__ A2,
    const float* __restrict__ W1, const float* __restrict__ W2,
    const float* __restrict__ bias, float* __restrict__ C,
    int M, int Ntot, int relu)
{
    __shared__ float As[BK][132];   // transposed A tile, padded stride
    __shared__ float Bs[BK][BN];
    int tid = threadIdx.x;
    int tx = tid & 15;   // -> N (4 cols each)
    int ty = tid >> 4;   // -> M (8 rows each)
    int bm = blockIdx.x * BM;
    int bn = blockIdx.y * BN;

    float acc[8][4];
    #pragma unroll
    for (int i = 0; i < 8; i++)
        #pragma unroll
        for (int j = 0; j < 4; j++) acc[i][j] = 0.f;

    for (int t = 0; t < 32; t++) {
        const float* A = (t < 16) ? A1 : A2;
        const float* W = (t < 16) ? W1 : W2;
        int k0 = (t & 15) * BK;
        // A tile: 128x16 -> transposed smem
        #pragma unroll
        for (int it = 0; it < 2; it++) {
            int idx = tid + it * 256;        // 0..511
            int row = idx >> 2;              // 0..127
            int kq = (idx & 3) * 4;
            int grow = bm + row;
            float4 v = make_float4(0.f, 0.f, 0.f, 0.f);
            if (grow < M)
                v = *(const float4*)(A + (long)grow * F + k0 + kq);
            As[kq + 0][row] = v.x;
            As[kq + 1][row] = v.y;
            As[kq + 2][row] = v.z;
            As[kq + 3][row] = v.w;
        }
        // B tile: 16x64
        {
            int krow = tid >> 4;
            int nq = (tid & 15) * 4;
            float4 v = *(const float4*)(W + (long)(k0 + krow) * Ntot + bn + nq);
            *(float4*)&Bs[krow][nq] = v;
        }
        __syncthreads();
        #pragma unroll
        for (int k = 0; k < BK; k++) {
            float4 aA = *(const float4*)&As[k][ty * 8];
            float4 aB = *(const float4*)&As[k][ty * 8 + 4];
            float4 bv = *(const float4*)&Bs[k][tx * 4];
            float a[8] = {aA.x, aA.y, aA.z, aA.w, aB.x, aB.y, aB.z, aB.w};
            float b[4] = {bv.x, bv.y, bv.z, bv.w};
            #pragma unroll
            for (int i = 0; i < 8; i++)
                #pragma unroll
                for (int j = 0; j < 4; j++)
                    acc[i][j] += a[i] * b[j];
        }
        __syncthreads();
    }

    float4 bb = *(const float4*)(bias + bn + tx * 4);
    float bj[4] = {bb.x, bb.y, bb.z, bb.w};
    #pragma unroll
    for (int i = 0; i < 8; i++) {
        int grow = bm + ty * 8 + i;
        if (grow < M) {
            float4 v;
            v.x = acc[i][0] + bj[0];
            v.y = acc[i][1] + bj[1];
            v.z = acc[i][2] + bj[2];
            v.w = acc[i][3] + bj[3];
            if (relu) {
                v.x = fmaxf(v.x, 0.f); v.y = fmaxf(v.y, 0.f);
                v.z = fmaxf(v.z, 0.f); v.w = fmaxf(v.w, 0.f);
            }
            *(float4*)(C + (long)grow * Ntot + bn + tx * 4) = v;
        }
    }
}

// ---------------- launch ------------------------------------------------------
extern "C" void kernel_launch(void* const* d_in, const int* in_sizes, int n_in,
                              void* d_out, int out_size) {
    const float* x   = (const float*)d_in[0];
    const int*   src = (const int*)d_in[1];
    const int*   dst = (const int*)d_in[2];
    const float* Ws0 = (const float*)d_in[3];
    const float* Wn0 = (const float*)d_in[4];
    const float* b0  = (const float*)d_in[5];
    const float* Ws1 = (const float*)d_in[6];
    const float* Wn1 = (const float*)d_in[7];
    const float* b1  = (const float*)d_in[8];
    const float* Ws2 = (const float*)d_in[9];
    const float* Wn2 = (const float*)d_in[10];
    const float* b2  = (const float*)d_in[11];

    float* out     = (float*)d_out;
    float* h_final = out;                          // [N, 64]  (tuple elem 0)
    float* h2      = out + (long)N_NODES * OUTF;   // [N, 256] (tuple elem 1)

    float* h1;  float* agg;  int* degp;
    cudaGetSymbolAddress((void**)&h1,  g_h1);
    cudaGetSymbolAddress((void**)&agg, g_agg);
    cudaGetSymbolAddress((void**)&degp, g_deg);

    // CSR build (same graph reused by all 3 layers)
    cudaMemsetAsync(degp, 0, N_NODES * sizeof(int));
    count_kernel<<<(N_EDGES + 255) / 256, 256>>>(dst);
    scan_kernel<<<1, 1024>>>();
    fill_kernel<<<(N_EDGES + 255) / 256, 256>>>(src, dst);

    dim3 g256((N_NODES + BM - 1) / BM, 256 / BN);  // 391 x 4
    dim3 g64((N_NODES + BM - 1) / BM, 1);          // 391 x 1

    // layer 0
    spmm_kernel<<<N_NODES, 256>>>(x, agg);
    gemm_kernel<<<g256, 256>>>(x, agg, Ws0, Wn0, b0, h1, N_NODES, 256, 1);
    // layer 1 (output doubles as tuple elem 1)
    spmm_kernel<<<N_NODES, 256>>>(h1, agg);
    gemm_kernel<<<g256, 256>>>(h1, agg, Ws1, Wn1, b1, h2, N_NODES, 256, 1);
    // layer 2 (no relu)
    spmm_kernel<<<N_NODES, 256>>>(h2, agg);
    gemm_kernel<<<g64, 256>>>(h2, agg, Ws2, Wn2, b2, h_final, N_NODES, 64, 0);
}

// round 3
// speedup vs baseline: 1.0623x; 1.0623x over previous
#include <cuda_runtime.h>

#define N_NODES 50000
#define N_EDGES 1600000
#define F 256
#define OUTF 64

// ---------------- scratch (static device globals; no runtime alloc) ----------
__device__ float g_h1[(long)N_NODES * F];    // layer-0 output
__device__ float g_agg[(long)N_NODES * F];   // neighbor-mean buffer (reused)
__device__ int   g_rowptr[N_NODES + 1];
__device__ int   g_cursor[N_NODES];
__device__ int   g_col[N_EDGES];
__device__ int   g_deg[N_NODES];
__device__ float g_invdeg[N_NODES];

// ---------------- CSR build ---------------------------------------------------
__global__ void count_kernel(const int* __restrict__ dst) {
    int e = blockIdx.x * blockDim.x + threadIdx.x;
    if (e < N_EDGES) atomicAdd(&g_deg[dst[e]], 1);
}

// single-block exclusive scan over 50000 degrees; also writes cursor + inv_deg
__global__ void scan_kernel() {
    __shared__ int sm[1024];
    __shared__ int carry_s;
    int tid = threadIdx.x;
    if (tid == 0) carry_s = 0;
    __syncthreads();
    for (int base = 0; base < N_NODES; base += 1024) {
        int idx = base + tid;
        int v = (idx < N_NODES) ? g_deg[idx] : 0;
        sm[tid] = v;
        __syncthreads();
        #pragma unroll
        for (int off = 1; off < 1024; off <<= 1) {
            int t = (tid >= off) ? sm[tid - off] : 0;
            __syncthreads();
            sm[tid] += t;
            __syncthreads();
        }
        int excl = carry_s + sm[tid] - v;
        if (idx < N_NODES) {
            g_rowptr[idx] = excl;
            g_cursor[idx] = excl;
            g_invdeg[idx] = 1.0f / (float)max(v, 1);
        }
        __syncthreads();
        if (tid == 1023) carry_s += sm[1023];
        __syncthreads();
    }
    if (tid == 0) g_rowptr[N_NODES] = carry_s;
}

__global__ void fill_kernel(const int* __restrict__ src, const int* __restrict__ dst) {
    int e = blockIdx.x * blockDim.x + threadIdx.x;
    if (e < N_EDGES) {
        int d = dst[e];
        int p = atomicAdd(&g_cursor[d], 1);
        g_col[p] = src[e];
    }
}

// ---------------- SpMM: out[n,:] = inv_deg[n] * sum h[col[e],:] --------------
// float4 lanes: 64 lanes per node, 4 nodes per 256-thread block.
// Column indices read as aligned int4 (uniform per warp -> broadcast wavefront).
__global__ __launch_bounds__(256) void spmm_kernel(const float4* __restrict__ h,
                                                   float4* __restrict__ out) {
    int group = threadIdx.x >> 6;        // node within block
    int lane  = threadIdx.x & 63;        // float4 feature lane (64 * 4 = 256)
    int n = blockIdx.x * 4 + group;
    if (n >= N_NODES) return;
    int s = g_rowptr[n];
    int e = g_rowptr[n + 1];

    float4 a0 = make_float4(0.f, 0.f, 0.f, 0.f);
    float4 a1 = a0, a2 = a0, a3 = a0;

    int i = s;
    int alignEnd = min(e, (s + 3) & ~3);
    for (; i < alignEnd; i++) {
        int c = __ldg(&g_col[i]);
        float4 v = h[(long)c * 64 + lane];
        a0.x += v.x; a0.y += v.y; a0.z += v.z; a0.w += v.w;
    }
    for (; i + 4 <= e; i += 4) {
        int4 c = *(const int4*)&g_col[i];            // 16B-aligned broadcast
        float4 v0 = h[(long)c.x * 64 + lane];
        float4 v1 = h[(long)c.y * 64 + lane];
        float4 v2 = h[(long)c.z * 64 + lane];
        float4 v3 = h[(long)c.w * 64 + lane];
        a0.x += v0.x; a0.y += v0.y; a0.z += v0.z; a0.w += v0.w;
        a1.x += v1.x; a1.y += v1.y; a1.z += v1.z; a1.w += v1.w;
        a2.x += v2.x; a2.y += v2.y; a2.z += v2.z; a2.w += v2.w;
        a3.x += v3.x; a3.y += v3.y; a3.z += v3.z; a3.w += v3.w;
    }
    for (; i < e; i++) {
        int c = __ldg(&g_col[i]);
        float4 v = h[(long)c * 64 + lane];
        a0.x += v.x; a0.y += v.y; a0.z += v.z; a0.w += v.w;
    }

    float d = g_invdeg[n];
    float4 r;
    r.x = (a0.x + a1.x + a2.x + a3.x) * d;
    r.y = (a0.y + a1.y + a2.y + a3.y) * d;
    r.z = (a0.z + a1.z + a2.z + a3.z) * d;
    r.w = (a0.w + a1.w + a2.w + a3.w) * d;
    out[(long)n * 64 + lane] = r;
}

// ---------------- fused dual-GEMM: C = relu?([A1|A2]@[W1;W2] + b) -------------
// BM=128, BK=16, double-buffered smem, register-staged global prefetch.
// BN=128 (TN=8) for 256-wide layers, BN=64 (TN=4) for the final layer.
#define BM 128
#define BK 16
#define TM 8

template<int BN, int TN, bool RELU>
__global__ __launch_bounds__(256, 2) void gemm_kernel(
    const float* __restrict__ A1, const float* __restrict__ A2,
    const float* __restrict__ W1, const float* __restrict__ W2,
    const float* __restrict__ bias, float* __restrict__ C,
    int M, int Ntot)
{
    constexpr int NTX = BN / TN;               // 16
    constexpr int BPT = (BK * BN) / (4 * 256); // float4 B-loads per thread (2 or 1)
    constexpr int COLS4 = BN / 4;

    __shared__ float As[2][BK][BM + 4];
    __shared__ float Bs[2][BK][BN];

    int tid = threadIdx.x;
    int tx = tid % NTX;
    int ty = tid / NTX;                        // 0..15 -> TM rows each
    int bm = blockIdx.x * BM;
    int bn = blockIdx.y * BN;

    float acc[TM][TN];
    #pragma unroll
    for (int i = 0; i < TM; i++)
        #pragma unroll
        for (int j = 0; j < TN; j++) acc[i][j] = 0.f;

    float4 aR[2];
    float4 bR[BPT];

    // per-thread A-load coords (512 float4 per tile / 256 threads = 2 each)
    int aRow[2], aKq[2];
    #pragma unroll
    for (int it = 0; it < 2; it++) {
        int idx = tid + it * 256;
        aRow[it] = idx >> 2;
        aKq[it]  = (idx & 3) * 4;
    }
    int bKrow[BPT], bNq[BPT];
    #pragma unroll
    for (int it = 0; it < BPT; it++) {
        int idx = tid + it * 256;
        bKrow[it] = idx / COLS4;
        bNq[it]   = (idx % COLS4) * 4;
    }

    auto loadRegs = [&](int t) {
        const float* A = (t < 16) ? A1 : A2;
        const float* W = (t < 16) ? W1 : W2;
        int k0 = (t & 15) * BK;
        #pragma unroll
        for (int it = 0; it < 2; it++) {
            int grow = bm + aRow[it];
            aR[it] = (grow < M)
                ? *(const float4*)(A + (long)grow * F + k0 + aKq[it])
                : make_float4(0.f, 0.f, 0.f, 0.f);
        }
        #pragma unroll
        for (int it = 0; it < BPT; it++)
            bR[it] = *(const float4*)(W + (long)(k0 + bKrow[it]) * Ntot + bn + bNq[it]);
    };
    auto storeSmem = [&](int p) {
        #pragma unroll
        for (int it = 0; it < 2; it++) {
            As[p][aKq[it] + 0][aRow[it]] = aR[it].x;
            As[p][aKq[it] + 1][aRow[it]] = aR[it].y;
            As[p][aKq[it] + 2][aRow[it]] = aR[it].z;
            As[p][aKq[it] + 3][aRow[it]] = aR[it].w;
        }
        #pragma unroll
        for (int it = 0; it < BPT; it++)
            *(float4*)&Bs[p][bKrow[it]][bNq[it]] = bR[it];
    };

    loadRegs(0);
    storeSmem(0);
    __syncthreads();

    for (int t = 0; t < 32; t++) {
        int p = t & 1;
        if (t < 31) loadRegs(t + 1);
        #pragma unroll
        for (int k = 0; k < BK; k++) {
            float af[TM], bf[TN];
            #pragma unroll
            for (int i4 = 0; i4 < TM / 4; i4++) {
                float4 v = *(const float4*)&As[p][k][ty * TM + i4 * 4];
                af[i4 * 4 + 0] = v.x; af[i4 * 4 + 1] = v.y;
                af[i4 * 4 + 2] = v.z; af[i4 * 4 + 3] = v.w;
            }
            #pragma unroll
            for (int j4 = 0; j4 < TN / 4; j4++) {
                float4 v = *(const float4*)&Bs[p][k][tx * TN + j4 * 4];
                bf[j4 * 4 + 0] = v.x; bf[j4 * 4 + 1] = v.y;
                bf[j4 * 4 + 2] = v.z; bf[j4 * 4 + 3] = v.w;
            }
            #pragma unroll
            for (int i = 0; i < TM; i++)
                #pragma unroll
                for (int j = 0; j < TN; j++)
                    acc[i][j] += af[i] * bf[j];
        }
        if (t < 31) storeSmem(p ^ 1);
        __syncthreads();
    }

    float bb[TN];
    #pragma unroll
    for (int j4 = 0; j4 < TN / 4; j4++) {
        float4 v = *(const float4*)(bias + bn + tx * TN + j4 * 4);
        bb[j4 * 4 + 0] = v.x; bb[j4 * 4 + 1] = v.y;
        bb[j4 * 4 + 2] = v.z; bb[j4 * 4 + 3] = v.w;
    }
    #pragma unroll
    for (int i = 0; i < TM; i++) {
        int grow = bm + ty * TM + i;
        if (grow < M) {
            #pragma unroll
            for (int j4 = 0; j4 < TN / 4; j4++) {
                float4 v;
                v.x = acc[i][j4 * 4 + 0] + bb[j4 * 4 + 0];
                v.y = acc[i][j4 * 4 + 1] + bb[j4 * 4 + 1];
                v.z = acc[i][j4 * 4 + 2] + bb[j4 * 4 + 2];
                v.w = acc[i][j4 * 4 + 3] + bb[j4 * 4 + 3];
                if (RELU) {
                    v.x = fmaxf(v.x, 0.f); v.y = fmaxf(v.y, 0.f);
                    v.z = fmaxf(v.z, 0.f); v.w = fmaxf(v.w, 0.f);
                }
                *(float4*)(C + (long)grow * Ntot + bn + tx * TN + j4 * 4) = v;
            }
        }
    }
}

// ---------------- launch ------------------------------------------------------
extern "C" void kernel_launch(void* const* d_in, const int* in_sizes, int n_in,
                              void* d_out, int out_size) {
    const float* x   = (const float*)d_in[0];
    const int*   src = (const int*)d_in[1];
    const int*   dst = (const int*)d_in[2];
    const float* Ws0 = (const float*)d_in[3];
    const float* Wn0 = (const float*)d_in[4];
    const float* b0  = (const float*)d_in[5];
    const float* Ws1 = (const float*)d_in[6];
    const float* Wn1 = (const float*)d_in[7];
    const float* b1  = (const float*)d_in[8];
    const float* Ws2 = (const float*)d_in[9];
    const float* Wn2 = (const float*)d_in[10];
    const float* b2  = (const float*)d_in[11];

    float* out     = (float*)d_out;
    float* h_final = out;                          // [N, 64]  (tuple elem 0)
    float* h2      = out + (long)N_NODES * OUTF;   // [N, 256] (tuple elem 1)

    float* h1;  float* agg;  int* degp;
    cudaGetSymbolAddress((void**)&h1,  g_h1);
    cudaGetSymbolAddress((void**)&agg, g_agg);
    cudaGetSymbolAddress((void**)&degp, g_deg);

    // CSR build (same graph reused by all 3 layers)
    cudaMemsetAsync(degp, 0, N_NODES * sizeof(int));
    count_kernel<<<(N_EDGES + 255) / 256, 256>>>(dst);
    scan_kernel<<<1, 1024>>>();
    fill_kernel<<<(N_EDGES + 255) / 256, 256>>>(src, dst);

    dim3 g256((N_NODES + BM - 1) / BM, 2);   // 391 x 2 (BN=128)
    dim3 g64((N_NODES + BM - 1) / BM, 1);    // 391 x 1 (BN=64)
    int spmmBlocks = (N_NODES + 3) / 4;

    // layer 0
    spmm_kernel<<<spmmBlocks, 256>>>((const float4*)x, (float4*)agg);
    gemm_kernel<128, 8, true><<<g256, 256>>>(x, agg, Ws0, Wn0, b0, h1, N_NODES, 256);
    // layer 1 (output doubles as tuple elem 1)
    spmm_kernel<<<spmmBlocks, 256>>>((const float4*)h1, (float4*)agg);
    gemm_kernel<128, 8, true><<<g256, 256>>>(h1, agg, Ws1, Wn1, b1, h2, N_NODES, 256);
    // layer 2 (no relu)
    spmm_kernel<<<spmmBlocks, 256>>>((const float4*)h2, (float4*)agg);
    gemm_kernel<64, 4, false><<<g64, 256>>>(h2, agg, Ws2, Wn2, b2, h_final, N_NODES, 64);
}

// round 4
// speedup vs baseline: 1.7998x; 1.6943x over previous
#include <cuda_runtime.h>

#define N_NODES 50000
#define N_EDGES 1600000
#define F 256
#define OUTF 64

// ---------------- scratch (static device globals; no runtime alloc) ----------
__device__ float g_h1[(long)N_NODES * F];    // layer-0 output
__device__ float g_agg[(long)N_NODES * F];   // neighbor-mean buffer (reused)
__device__ int   g_rowptr[N_NODES + 1];
__device__ int   g_cursor[N_NODES];
__device__ int   g_col[N_EDGES];
__device__ int   g_deg[N_NODES];
__device__ float g_invdeg[N_NODES];

// ---------------- CSR build ---------------------------------------------------
__global__ void count_kernel(const int* __restrict__ dst) {
    int e = blockIdx.x * blockDim.x + threadIdx.x;
    if (e < N_EDGES) atomicAdd(&g_deg[dst[e]], 1);
}

__global__ void scan_kernel() {
    __shared__ int sm[1024];
    __shared__ int carry_s;
    int tid = threadIdx.x;
    if (tid == 0) carry_s = 0;
    __syncthreads();
    for (int base = 0; base < N_NODES; base += 1024) {
        int idx = base + tid;
        int v = (idx < N_NODES) ? g_deg[idx] : 0;
        sm[tid] = v;
        __syncthreads();
        #pragma unroll
        for (int off = 1; off < 1024; off <<= 1) {
            int t = (tid >= off) ? sm[tid - off] : 0;
            __syncthreads();
            sm[tid] += t;
            __syncthreads();
        }
        int excl = carry_s + sm[tid] - v;
        if (idx < N_NODES) {
            g_rowptr[idx] = excl;
            g_cursor[idx] = excl;
            g_invdeg[idx] = 1.0f / (float)max(v, 1);
        }
        __syncthreads();
        if (tid == 1023) carry_s += sm[1023];
        __syncthreads();
    }
    if (tid == 0) g_rowptr[N_NODES] = carry_s;
}

__global__ void fill_kernel(const int* __restrict__ src, const int* __restrict__ dst) {
    int e = blockIdx.x * blockDim.x + threadIdx.x;
    if (e < N_EDGES) {
        int d = dst[e];
        int p = atomicAdd(&g_cursor[d], 1);
        g_col[p] = src[e];
    }
}

// ---------------- SpMM (unchanged from round 3) -------------------------------
__global__ __launch_bounds__(256) void spmm_kernel(const float4* __restrict__ h,
                                                   float4* __restrict__ out) {
    int group = threadIdx.x >> 6;
    int lane  = threadIdx.x & 63;
    int n = blockIdx.x * 4 + group;
    if (n >= N_NODES) return;
    int s = g_rowptr[n];
    int e = g_rowptr[n + 1];

    float4 a0 = make_float4(0.f, 0.f, 0.f, 0.f);
    float4 a1 = a0, a2 = a0, a3 = a0;

    int i = s;
    int alignEnd = min(e, (s + 3) & ~3);
    for (; i < alignEnd; i++) {
        int c = __ldg(&g_col[i]);
        float4 v = h[(long)c * 64 + lane];
        a0.x += v.x; a0.y += v.y; a0.z += v.z; a0.w += v.w;
    }
    for (; i + 4 <= e; i += 4) {
        int4 c = *(const int4*)&g_col[i];
        float4 v0 = h[(long)c.x * 64 + lane];
        float4 v1 = h[(long)c.y * 64 + lane];
        float4 v2 = h[(long)c.z * 64 + lane];
        float4 v3 = h[(long)c.w * 64 + lane];
        a0.x += v0.x; a0.y += v0.y; a0.z += v0.z; a0.w += v0.w;
        a1.x += v1.x; a1.y += v1.y; a1.z += v1.z; a1.w += v1.w;
        a2.x += v2.x; a2.y += v2.y; a2.z += v2.z; a2.w += v2.w;
        a3.x += v3.x; a3.y += v3.y; a3.z += v3.z; a3.w += v3.w;
    }
    for (; i < e; i++) {
        int c = __ldg(&g_col[i]);
        float4 v = h[(long)c * 64 + lane];
        a0.x += v.x; a0.y += v.y; a0.z += v.z; a0.w += v.w;
    }

    float d = g_invdeg[n];
    float4 r;
    r.x = (a0.x + a1.x + a2.x + a3.x) * d;
    r.y = (a0.y + a1.y + a2.y + a3.y) * d;
    r.z = (a0.z + a1.z + a2.z + a3.z) * d;
    r.w = (a0.w + a1.w + a2.w + a3.w) * d;
    out[(long)n * 64 + lane] = r;
}

// ---------------- tf32 tensor-core dual-GEMM ---------------------------------
// C = relu?([A1|A2] @ [W1;W2] + b), K = 256 per half.
// BM=128, BK=16, BN=128 or 64. 8 warps = 2(m) x 4(n), warp tile 64 x BN/4.
// mma.sync.m16n8k8 tf32, double-buffered smem, register-staged prefetch.

__device__ __forceinline__ float f2tf32(float x) {
    unsigned r;
    asm("cvt.rna.tf32.f32 %0, %1;" : "=r"(r) : "f"(x));
    return __uint_as_float(r);
}

#define MMA_TF32(d0, d1, d2, d3, a0, a1, a2, a3, b0, b1)                    \
    asm volatile(                                                           \
        "mma.sync.aligned.m16n8k8.row.col.f32.tf32.tf32.f32 "               \
        "{%0,%1,%2,%3}, {%4,%5,%6,%7}, {%8,%9}, {%0,%1,%2,%3};"             \
        : "+f"(d0), "+f"(d1), "+f"(d2), "+f"(d3)                            \
        : "r"(a0), "r"(a1), "r"(a2), "r"(a3), "r"(b0), "r"(b1))

template<int BN, bool RELU>
__global__ __launch_bounds__(256) void gemm_tc(
    const float* __restrict__ A1, const float* __restrict__ A2,
    const float* __restrict__ W1, const float* __restrict__ W2,
    const float* __restrict__ bias, float* __restrict__ C,
    int M, int Ntot)
{
    constexpr int BM = 128, BK = 16;
    constexpr int APAD = BK + 4;            // 20
    constexpr int BPAD = BN + 4;            // 132 / 68
    constexpr int NT   = BN / 32;           // n-tiles per warp (4 / 2)
    constexpr int BLD  = (BK * BN) / (4 * 256);  // float4 B-loads/thread (2 / 1)
    constexpr int COLS4 = BN / 4;

    __shared__ float As[2][BM][APAD];
    __shared__ float Bs[2][BK][BPAD];

    int tid  = threadIdx.x;
    int wid  = tid >> 5;
    int lane = tid & 31;
    int wm = wid >> 2;        // 0..1 -> 64 rows each
    int wn = wid & 3;         // 0..3 -> BN/4 cols each
    int lr = lane >> 2;       // 0..7
    int lc = lane & 3;        // 0..3
    int bm = blockIdx.x * BM;
    int bn = blockIdx.y * BN;

    float acc[4][NT][4];
    #pragma unroll
    for (int mt = 0; mt < 4; mt++)
        #pragma unroll
        for (int nt = 0; nt < NT; nt++)
            #pragma unroll
            for (int r = 0; r < 4; r++) acc[mt][nt][r] = 0.f;

    // per-thread load coords
    int aRow[2], aKq[2];
    #pragma unroll
    for (int it = 0; it < 2; it++) {
        int idx = tid + it * 256;
        aRow[it] = idx >> 2;
        aKq[it]  = (idx & 3) * 4;
    }
    int bKrow[BLD], bNq[BLD];
    #pragma unroll
    for (int it = 0; it < BLD; it++) {
        int idx = tid + it * 256;
        bKrow[it] = idx / COLS4;
        bNq[it]   = (idx % COLS4) * 4;
    }

    float4 aR[2], bR[BLD];
    auto loadRegs = [&](int t) {
        const float* A = (t < 16) ? A1 : A2;
        const float* W = (t < 16) ? W1 : W2;
        int k0 = (t & 15) * BK;
        #pragma unroll
        for (int it = 0; it < 2; it++) {
            int grow = bm + aRow[it];
            aR[it] = (grow < M)
                ? *(const float4*)(A + (long)grow * F + k0 + aKq[it])
                : make_float4(0.f, 0.f, 0.f, 0.f);
        }
        #pragma unroll
        for (int it = 0; it < BLD; it++)
            bR[it] = *(const float4*)(W + (long)(k0 + bKrow[it]) * Ntot + bn + bNq[it]);
    };
    auto storeSmem = [&](int p) {
        #pragma unroll
        for (int it = 0; it < 2; it++) {
            float4 v;
            v.x = f2tf32(aR[it].x); v.y = f2tf32(aR[it].y);
            v.z = f2tf32(aR[it].z); v.w = f2tf32(aR[it].w);
            *(float4*)&As[p][aRow[it]][aKq[it]] = v;
        }
        #pragma unroll
        for (int it = 0; it < BLD; it++) {
            float4 v;
            v.x = f2tf32(bR[it].x); v.y = f2tf32(bR[it].y);
            v.z = f2tf32(bR[it].z); v.w = f2tf32(bR[it].w);
            *(float4*)&Bs[p][bKrow[it]][bNq[it]] = v;
        }
    };

    loadRegs(0);
    storeSmem(0);
    __syncthreads();

    for (int t = 0; t < 32; t++) {
        int p = t & 1;
        if (t < 31) loadRegs(t + 1);
        #pragma unroll
        for (int ks = 0; ks < 2; ks++) {
            int k0 = ks * 8;
            unsigned af[4][4];
            #pragma unroll
            for (int mt = 0; mt < 4; mt++) {
                int rb = wm * 64 + mt * 16 + lr;
                af[mt][0] = __float_as_uint(As[p][rb    ][k0 + lc    ]);
                af[mt][1] = __float_as_uint(As[p][rb + 8][k0 + lc    ]);
                af[mt][2] = __float_as_uint(As[p][rb    ][k0 + lc + 4]);
                af[mt][3] = __float_as_uint(As[p][rb + 8][k0 + lc + 4]);
            }
            unsigned bf[NT][2];
            #pragma unroll
            for (int nt = 0; nt < NT; nt++) {
                int cb = wn * (BN / 4) + nt * 8 + lr;
                bf[nt][0] = __float_as_uint(Bs[p][k0 + lc    ][cb]);
                bf[nt][1] = __float_as_uint(Bs[p][k0 + lc + 4][cb]);
            }
            #pragma unroll
            for (int mt = 0; mt < 4; mt++)
                #pragma unroll
                for (int nt = 0; nt < NT; nt++)
                    MMA_TF32(acc[mt][nt][0], acc[mt][nt][1],
                             acc[mt][nt][2], acc[mt][nt][3],
                             af[mt][0], af[mt][1], af[mt][2], af[mt][3],
                             bf[nt][0], bf[nt][1]);
        }
        if (t < 31) storeSmem(p ^ 1);
        __syncthreads();
    }

    // epilogue: bias + optional relu, float2 stores
    #pragma unroll
    for (int nt = 0; nt < NT; nt++) {
        int gcol = bn + wn * (BN / 4) + nt * 8 + 2 * lc;
        float2 bb = *(const float2*)(bias + gcol);
        #pragma unroll
        for (int mt = 0; mt < 4; mt++) {
            int row0 = bm + wm * 64 + mt * 16 + lr;
            float2 v0, v1;
            v0.x = acc[mt][nt][0] + bb.x;  v0.y = acc[mt][nt][1] + bb.y;
            v1.x = acc[mt][nt][2] + bb.x;  v1.y = acc[mt][nt][3] + bb.y;
            if (RELU) {
                v0.x = fmaxf(v0.x, 0.f); v0.y = fmaxf(v0.y, 0.f);
                v1.x = fmaxf(v1.x, 0.f); v1.y = fmaxf(v1.y, 0.f);
            }
            if (row0 < M)     *(float2*)(C + (long)row0 * Ntot + gcol) = v0;
            if (row0 + 8 < M) *(float2*)(C + (long)(row0 + 8) * Ntot + gcol) = v1;
        }
    }
}

// ---------------- launch ------------------------------------------------------
extern "C" void kernel_launch(void* const* d_in, const int* in_sizes, int n_in,
                              void* d_out, int out_size) {
    const float* x   = (const float*)d_in[0];
    const int*   src = (const int*)d_in[1];
    const int*   dst = (const int*)d_in[2];
    const float* Ws0 = (const float*)d_in[3];
    const float* Wn0 = (const float*)d_in[4];
    const float* b0  = (const float*)d_in[5];
    const float* Ws1 = (const float*)d_in[6];
    const float* Wn1 = (const float*)d_in[7];
    const float* b1  = (const float*)d_in[8];
    const float* Ws2 = (const float*)d_in[9];
    const float* Wn2 = (const float*)d_in[10];
    const float* b2  = (const float*)d_in[11];

    float* out     = (float*)d_out;
    float* h_final = out;                          // [N, 64]  (tuple elem 0)
    float* h2      = out + (long)N_NODES * OUTF;   // [N, 256] (tuple elem 1)

    float* h1;  float* agg;  int* degp;
    cudaGetSymbolAddress((void**)&h1,  g_h1);
    cudaGetSymbolAddress((void**)&agg, g_agg);
    cudaGetSymbolAddress((void**)&degp, g_deg);

    // CSR build (same graph reused by all 3 layers)
    cudaMemsetAsync(degp, 0, N_NODES * sizeof(int));
    count_kernel<<<(N_EDGES + 255) / 256, 256>>>(dst);
    scan_kernel<<<1, 1024>>>();
    fill_kernel<<<(N_EDGES + 255) / 256, 256>>>(src, dst);

    dim3 g256((N_NODES + 127) / 128, 2);   // 391 x 2 (BN=128)
    dim3 g64((N_NODES + 127) / 128, 1);    // 391 x 1 (BN=64)
    int spmmBlocks = (N_NODES + 3) / 4;

    // layer 0
    spmm_kernel<<<spmmBlocks, 256>>>((const float4*)x, (float4*)agg);
    gemm_tc<128, true><<<g256, 256>>>(x, agg, Ws0, Wn0, b0, h1, N_NODES, 256);
    // layer 1 (output doubles as tuple elem 1)
    spmm_kernel<<<spmmBlocks, 256>>>((const float4*)h1, (float4*)agg);
    gemm_tc<128, true><<<g256, 256>>>(h1, agg, Ws1, Wn1, b1, h2, N_NODES, 256);
    // layer 2 (no relu)
    spmm_kernel<<<spmmBlocks, 256>>>((const float4*)h2, (float4*)agg);
    gemm_tc<64, false><<<g64, 256>>>(h2, agg, Ws2, Wn2, b2, h_final, N_NODES, 64);
}

// round 5
// speedup vs baseline: 1.8379x; 1.0212x over previous
#include <cuda_runtime.h>

#define N_NODES 50000
#define N_EDGES 1600000
#define F 256
#define OUTF 64

// ---------------- scratch (static device globals; no runtime alloc) ----------
__device__ float g_h1[(long)N_NODES * F];    // layer-0 output
__device__ float g_ys[(long)N_NODES * F];    // self-term buffer
__device__ float g_yn[(long)N_NODES * F];    // neighbor-term (pre-agg) buffer
__device__ int   g_rowptr[N_NODES + 1];
__device__ int   g_cursor[N_NODES];
__device__ int   g_col[N_EDGES];
__device__ int   g_deg[N_NODES];
__device__ float g_invdeg[N_NODES];

// ---------------- CSR build ---------------------------------------------------
__global__ void count_kernel(const int* __restrict__ dst) {
    int e = blockIdx.x * blockDim.x + threadIdx.x;
    if (e < N_EDGES) atomicAdd(&g_deg[dst[e]], 1);
}

// single-block chunked exclusive scan: serial-local -> 1024-scan -> add-back
__global__ __launch_bounds__(1024) void scan_kernel() {
    __shared__ int sm[1024];
    const int CH = (N_NODES + 1023) / 1024;   // 49
    int tid = threadIdx.x;
    int start = tid * CH;
    int end = min(start + CH, N_NODES);
    int local = 0;
    for (int i = start; i < end; i++) local += g_deg[i];
    sm[tid] = local;
    __syncthreads();
    #pragma unroll
    for (int off = 1; off < 1024; off <<= 1) {
        int t = (tid >= off) ? sm[tid - off] : 0;
        __syncthreads();
        sm[tid] += t;
        __syncthreads();
    }
    int run = sm[tid] - local;                 // exclusive prefix of chunk
    for (int i = start; i < end; i++) {
        int v = g_deg[i];
        g_rowptr[i] = run;
        g_cursor[i] = run;
        g_invdeg[i] = 1.0f / (float)max(v, 1);
        run += v;
    }
    if (tid == 0) g_rowptr[N_NODES] = sm[1023];
}

__global__ void fill_kernel(const int* __restrict__ src, const int* __restrict__ dst) {
    int e = blockIdx.x * blockDim.x + threadIdx.x;
    if (e < N_EDGES) {
        int d = dst[e];
        int p = atomicAdd(&g_cursor[d], 1);
        g_col[p] = src[e];
    }
}

// ---------------- SpMM + epilogue: out = relu?(ys + invdeg * sum yn[src]) -----
// L4 = float4 lanes per node (64 for 256-dim, 16 for 64-dim)
template<int L4, bool RELU>
__global__ __launch_bounds__(256) void spmm_add_kernel(
    const float4* __restrict__ yn, const float4* __restrict__ ys,
    float4* __restrict__ out)
{
    constexpr int NPB = 256 / L4;
    int group = threadIdx.x / L4;
    int lane  = threadIdx.x % L4;
    int n = blockIdx.x * NPB + group;
    if (n >= N_NODES) return;
    int s = g_rowptr[n];
    int e = g_rowptr[n + 1];

    float4 a0 = make_float4(0.f, 0.f, 0.f, 0.f);
    float4 a1 = a0, a2 = a0, a3 = a0;

    int i = s;
    int alignEnd = min(e, (s + 3) & ~3);
    for (; i < alignEnd; i++) {
        int c = __ldg(&g_col[i]);
        float4 v = yn[(long)c * L4 + lane];
        a0.x += v.x; a0.y += v.y; a0.z += v.z; a0.w += v.w;
    }
    for (; i + 4 <= e; i += 4) {
        int4 c = *(const int4*)&g_col[i];
        float4 v0 = yn[(long)c.x * L4 + lane];
        float4 v1 = yn[(long)c.y * L4 + lane];
        float4 v2 = yn[(long)c.z * L4 + lane];
        float4 v3 = yn[(long)c.w * L4 + lane];
        a0.x += v0.x; a0.y += v0.y; a0.z += v0.z; a0.w += v0.w;
        a1.x += v1.x; a1.y += v1.y; a1.z += v1.z; a1.w += v1.w;
        a2.x += v2.x; a2.y += v2.y; a2.z += v2.z; a2.w += v2.w;
        a3.x += v3.x; a3.y += v3.y; a3.z += v3.z; a3.w += v3.w;
    }
    for (; i < e; i++) {
        int c = __ldg(&g_col[i]);
        float4 v = yn[(long)c * L4 + lane];
        a0.x += v.x; a0.y += v.y; a0.z += v.z; a0.w += v.w;
    }

    float d = g_invdeg[n];
    float4 sv = ys[(long)n * L4 + lane];
    float4 r;
    r.x = sv.x + (a0.x + a1.x + a2.x + a3.x) * d;
    r.y = sv.y + (a0.y + a1.y + a2.y + a3.y) * d;
    r.z = sv.z + (a0.z + a1.z + a2.z + a3.z) * d;
    r.w = sv.w + (a0.w + a1.w + a2.w + a3.w) * d;
    if (RELU) {
        r.x = fmaxf(r.x, 0.f); r.y = fmaxf(r.y, 0.f);
        r.z = fmaxf(r.z, 0.f); r.w = fmaxf(r.w, 0.f);
    }
    out[(long)n * L4 + lane] = r;
}

// ---------------- tf32 tensor-core GEMM: Ys = A@Wself + b, Yn = A@Wneigh ------
// K = 256 (16 k-tiles). blockIdx.y selects {W_self -> Ys (+bias)} or
// {W_neigh -> Yn}. BM=128, BK=16, BN=128 or 64. 8 warps = 2(m) x 4(n).

__device__ __forceinline__ float f2tf32(float x) {
    unsigned r;
    asm("cvt.rna.tf32.f32 %0, %1;" : "=r"(r) : "f"(x));
    return __uint_as_float(r);
}

#define MMA_TF32(d0, d1, d2, d3, a0, a1, a2, a3, b0, b1)                    \
    asm volatile(                                                           \
        "mma.sync.aligned.m16n8k8.row.col.f32.tf32.tf32.f32 "               \
        "{%0,%1,%2,%3}, {%4,%5,%6,%7}, {%8,%9}, {%0,%1,%2,%3};"             \
        : "+f"(d0), "+f"(d1), "+f"(d2), "+f"(d3)                            \
        : "r"(a0), "r"(a1), "r"(a2), "r"(a3), "r"(b0), "r"(b1))

template<int BN>
__global__ __launch_bounds__(256) void gemm_tc(
    const float* __restrict__ A,
    const float* __restrict__ Wself, const float* __restrict__ Wneigh,
    const float* __restrict__ bias,
    float* __restrict__ Ys, float* __restrict__ Yn,
    int M, int Nout)
{
    constexpr int BM = 128, BK = 16;
    constexpr int APAD = BK + 4;
    constexpr int BPAD = BN + 4;
    constexpr int NT   = BN / 32;
    constexpr int BLD  = (BK * BN) / (4 * 256);
    constexpr int COLS4 = BN / 4;

    __shared__ float As[2][BM][APAD];
    __shared__ float Bs[2][BK][BPAD];

    int tid  = threadIdx.x;
    int wid  = tid >> 5;
    int lane = tid & 31;
    int wm = wid >> 2;
    int wn = wid & 3;
    int lr = lane >> 2;
    int lc = lane & 3;
    int bm = blockIdx.x * BM;

    int tilesPerHalf = Nout / BN;
    int sel = blockIdx.y / tilesPerHalf;           // 0: self, 1: neigh
    int bn  = (blockIdx.y % tilesPerHalf) * BN;
    const float* W = sel ? Wneigh : Wself;
    float* C = sel ? Yn : Ys;

    float acc[4][NT][4];
    #pragma unroll
    for (int mt = 0; mt < 4; mt++)
        #pragma unroll
        for (int nt = 0; nt < NT; nt++)
            #pragma unroll
            for (int r = 0; r < 4; r++) acc[mt][nt][r] = 0.f;

    int aRow[2], aKq[2];
    #pragma unroll
    for (int it = 0; it < 2; it++) {
        int idx = tid + it * 256;
        aRow[it] = idx >> 2;
        aKq[it]  = (idx & 3) * 4;
    }
    int bKrow[BLD], bNq[BLD];
    #pragma unroll
    for (int it = 0; it < BLD; it++) {
        int idx = tid + it * 256;
        bKrow[it] = idx / COLS4;
        bNq[it]   = (idx % COLS4) * 4;
    }

    float4 aR[2], bR[BLD];
    auto loadRegs = [&](int t) {
        int k0 = t * BK;
        #pragma unroll
        for (int it = 0; it < 2; it++) {
            int grow = bm + aRow[it];
            aR[it] = (grow < M)
                ? *(const float4*)(A + (long)grow * F + k0 + aKq[it])
                : make_float4(0.f, 0.f, 0.f, 0.f);
        }
        #pragma unroll
        for (int it = 0; it < BLD; it++)
            bR[it] = *(const float4*)(W + (long)(k0 + bKrow[it]) * Nout + bn + bNq[it]);
    };
    auto storeSmem = [&](int p) {
        #pragma unroll
        for (int it = 0; it < 2; it++) {
            float4 v;
            v.x = f2tf32(aR[it].x); v.y = f2tf32(aR[it].y);
            v.z = f2tf32(aR[it].z); v.w = f2tf32(aR[it].w);
            *(float4*)&As[p][aRow[it]][aKq[it]] = v;
        }
        #pragma unroll
        for (int it = 0; it < BLD; it++) {
            float4 v;
            v.x = f2tf32(bR[it].x); v.y = f2tf32(bR[it].y);
            v.z = f2tf32(bR[it].z); v.w = f2tf32(bR[it].w);
            *(float4*)&Bs[p][bKrow[it]][bNq[it]] = v;
        }
    };

    loadRegs(0);
    storeSmem(0);
    __syncthreads();

    for (int t = 0; t < 16; t++) {
        int p = t & 1;
        if (t < 15) loadRegs(t + 1);
        #pragma unroll
        for (int ks = 0; ks < 2; ks++) {
            int k0 = ks * 8;
            unsigned af[4][4];
            #pragma unroll
            for (int mt = 0; mt < 4; mt++) {
                int rb = wm * 64 + mt * 16 + lr;
                af[mt][0] = __float_as_uint(As[p][rb    ][k0 + lc    ]);
                af[mt][1] = __float_as_uint(As[p][rb + 8][k0 + lc    ]);
                af[mt][2] = __float_as_uint(As[p][rb    ][k0 + lc + 4]);
                af[mt][3] = __float_as_uint(As[p][rb + 8][k0 + lc + 4]);
            }
            unsigned bf[NT][2];
            #pragma unroll
            for (int nt = 0; nt < NT; nt++) {
                int cb = wn * (BN / 4) + nt * 8 + lr;
                bf[nt][0] = __float_as_uint(Bs[p][k0 + lc    ][cb]);
                bf[nt][1] = __float_as_uint(Bs[p][k0 + lc + 4][cb]);
            }
            #pragma unroll
            for (int mt = 0; mt < 4; mt++)
                #pragma unroll
                for (int nt = 0; nt < NT; nt++)
                    MMA_TF32(acc[mt][nt][0], acc[mt][nt][1],
                             acc[mt][nt][2], acc[mt][nt][3],
                             af[mt][0], af[mt][1], af[mt][2], af[mt][3],
                             bf[nt][0], bf[nt][1]);
        }
        if (t < 15) storeSmem(p ^ 1);
        __syncthreads();
    }

    // epilogue: bias only for the self half
    #pragma unroll
    for (int nt = 0; nt < NT; nt++) {
        int gcol = bn + wn * (BN / 4) + nt * 8 + 2 * lc;
        float2 bb = make_float2(0.f, 0.f);
        if (sel == 0) bb = *(const float2*)(bias + gcol);
        #pragma unroll
        for (int mt = 0; mt < 4; mt++) {
            int row0 = bm + wm * 64 + mt * 16 + lr;
            float2 v0, v1;
            v0.x = acc[mt][nt][0] + bb.x;  v0.y = acc[mt][nt][1] + bb.y;
            v1.x = acc[mt][nt][2] + bb.x;  v1.y = acc[mt][nt][3] + bb.y;
            if (row0 < M)     *(float2*)(C + (long)row0 * Nout + gcol) = v0;
            if (row0 + 8 < M) *(float2*)(C + (long)(row0 + 8) * Nout + gcol) = v1;
        }
    }
}

// ---------------- launch ------------------------------------------------------
extern "C" void kernel_launch(void* const* d_in, const int* in_sizes, int n_in,
                              void* d_out, int out_size) {
    const float* x   = (const float*)d_in[0];
    const int*   src = (const int*)d_in[1];
    const int*   dst = (const int*)d_in[2];
    const float* Ws0 = (const float*)d_in[3];
    const float* Wn0 = (const float*)d_in[4];
    const float* b0  = (const float*)d_in[5];
    const float* Ws1 = (const float*)d_in[6];
    const float* Wn1 = (const float*)d_in[7];
    const float* b1  = (const float*)d_in[8];
    const float* Ws2 = (const float*)d_in[9];
    const float* Wn2 = (const float*)d_in[10];
    const float* b2  = (const float*)d_in[11];

    float* out     = (float*)d_out;
    float* h_final = out;                          // [N, 64]  (tuple elem 0)
    float* h2      = out + (long)N_NODES * OUTF;   // [N, 256] (tuple elem 1)

    float* h1;  float* ys;  float* yn;  int* degp;
    cudaGetSymbolAddress((void**)&h1, g_h1);
    cudaGetSymbolAddress((void**)&ys, g_ys);
    cudaGetSymbolAddress((void**)&yn, g_yn);
    cudaGetSymbolAddress((void**)&degp, g_deg);

    // CSR build (same graph reused by all 3 layers)
    cudaMemsetAsync(degp, 0, N_NODES * sizeof(int));
    count_kernel<<<(N_EDGES + 255) / 256, 256>>>(dst);
    scan_kernel<<<1, 1024>>>();
    fill_kernel<<<(N_EDGES + 255) / 256, 256>>>(src, dst);

    dim3 g256((N_NODES + 127) / 128, 4);   // BN=128, Nout=256: 2 tiles x 2 halves
    dim3 g64((N_NODES + 127) / 128, 2);    // BN=64,  Nout=64:  1 tile  x 2 halves

    // layer 0
    gemm_tc<128><<<g256, 256>>>(x, Ws0, Wn0, b0, ys, yn, N_NODES, 256);
    spmm_add_kernel<64, true><<<(N_NODES + 3) / 4, 256>>>(
        (const float4*)yn, (const float4*)ys, (float4*)h1);
    // layer 1 (output doubles as tuple elem 1)
    gemm_tc<128><<<g256, 256>>>(h1, Ws1, Wn1, b1, ys, yn, N_NODES, 256);
    spmm_add_kernel<64, true><<<(N_NODES + 3) / 4, 256>>>(
        (const float4*)yn, (const float4*)ys, (float4*)h2);
    // layer 2 (64-dim aggregation, no relu)
    gemm_tc<64><<<g64, 256>>>(h2, Ws2, Wn2, b2, ys, yn, N_NODES, 64);
    spmm_add_kernel<16, false><<<(N_NODES + 15) / 16, 256>>>(
        (const float4*)yn, (const float4*)ys, (float4*)h_final);
}

// round 6
// speedup vs baseline: 1.8422x; 1.0023x over previous
#include <cuda_runtime.h>

#define N_NODES 50000
#define N_EDGES 1600000
#define F 256
#define OUTF 64

// ---------------- scratch (static device globals; no runtime alloc) ----------
__device__ float g_h1[(long)N_NODES * F];    // layer-0 output
__device__ float g_ys[(long)N_NODES * F];    // self-term buffer
__device__ float g_yn[(long)N_NODES * F];    // neighbor-term (pre-agg) buffer
__device__ int   g_rowptr[N_NODES + 1];
__device__ int   g_cursor[N_NODES];
__device__ int   g_col[N_EDGES];
__device__ int   g_deg[N_NODES];
__device__ float g_invdeg[N_NODES];

// ---------------- CSR build ---------------------------------------------------
__global__ void count_kernel(const int* __restrict__ dst) {
    int e = blockIdx.x * blockDim.x + threadIdx.x;
    if (e < N_EDGES) atomicAdd(&g_deg[dst[e]], 1);
}

// single-block chunked exclusive scan: serial-local -> 1024-scan -> add-back
__global__ __launch_bounds__(1024) void scan_kernel() {
    __shared__ int sm[1024];
    const int CH = (N_NODES + 1023) / 1024;   // 49
    int tid = threadIdx.x;
    int start = tid * CH;
    int end = min(start + CH, N_NODES);
    int local = 0;
    for (int i = start; i < end; i++) local += g_deg[i];
    sm[tid] = local;
    __syncthreads();
    #pragma unroll
    for (int off = 1; off < 1024; off <<= 1) {
        int t = (tid >= off) ? sm[tid - off] : 0;
        __syncthreads();
        sm[tid] += t;
        __syncthreads();
    }
    int run = sm[tid] - local;                 // exclusive prefix of chunk
    for (int i = start; i < end; i++) {
        int v = g_deg[i];
        g_rowptr[i] = run;
        g_cursor[i] = run;
        g_invdeg[i] = 1.0f / (float)max(v, 1);
        run += v;
    }
    if (tid == 0) g_rowptr[N_NODES] = sm[1023];
}

__global__ void fill_kernel(const int* __restrict__ src, const int* __restrict__ dst) {
    int e = blockIdx.x * blockDim.x + threadIdx.x;
    if (e < N_EDGES) {
        int d = dst[e];
        int p = atomicAdd(&g_cursor[d], 1);
        g_col[p] = src[e];
    }
}

// ---------------- SpMM + epilogue: out = relu?(ys + invdeg * sum yn[src]) -----
// L4 = float4 lanes per node (64 for 256-dim, 16 for 64-dim)
template<int L4, bool RELU>
__global__ __launch_bounds__(256) void spmm_add_kernel(
    const float4* __restrict__ yn, const float4* __restrict__ ys,
    float4* __restrict__ out)
{
    constexpr int NPB = 256 / L4;
    int group = threadIdx.x / L4;
    int lane  = threadIdx.x % L4;
    int n = blockIdx.x * NPB + group;
    if (n >= N_NODES) return;
    int s = g_rowptr[n];
    int e = g_rowptr[n + 1];

    float4 a0 = make_float4(0.f, 0.f, 0.f, 0.f);
    float4 a1 = a0, a2 = a0, a3 = a0;

    int i = s;
    int alignEnd = min(e, (s + 3) & ~3);
    for (; i < alignEnd; i++) {
        int c = __ldg(&g_col[i]);
        float4 v = yn[(long)c * L4 + lane];
        a0.x += v.x; a0.y += v.y; a0.z += v.z; a0.w += v.w;
    }
    for (; i + 4 <= e; i += 4) {
        int4 c = *(const int4*)&g_col[i];
        float4 v0 = yn[(long)c.x * L4 + lane];
        float4 v1 = yn[(long)c.y * L4 + lane];
        float4 v2 = yn[(long)c.z * L4 + lane];
        float4 v3 = yn[(long)c.w * L4 + lane];
        a0.x += v0.x; a0.y += v0.y; a0.z += v0.z; a0.w += v0.w;
        a1.x += v1.x; a1.y += v1.y; a1.z += v1.z; a1.w += v1.w;
        a2.x += v2.x; a2.y += v2.y; a2.z += v2.z; a2.w += v2.w;
        a3.x += v3.x; a3.y += v3.y; a3.z += v3.z; a3.w += v3.w;
    }
    for (; i < e; i++) {
        int c = __ldg(&g_col[i]);
        float4 v = yn[(long)c * L4 + lane];
        a0.x += v.x; a0.y += v.y; a0.z += v.z; a0.w += v.w;
    }

    float d = g_invdeg[n];
    float4 sv = ys[(long)n * L4 + lane];
    float4 r;
    r.x = sv.x + (a0.x + a1.x + a2.x + a3.x) * d;
    r.y = sv.y + (a0.y + a1.y + a2.y + a3.y) * d;
    r.z = sv.z + (a0.z + a1.z + a2.z + a3.z) * d;
    r.w = sv.w + (a0.w + a1.w + a2.w + a3.w) * d;
    if (RELU) {
        r.x = fmaxf(r.x, 0.f); r.y = fmaxf(r.y, 0.f);
        r.z = fmaxf(r.z, 0.f); r.w = fmaxf(r.w, 0.f);
    }
    out[(long)n * L4 + lane] = r;
}

// ---------------- tf32 tensor-core GEMM: Ys = A@Wself + b, Yn = A@Wneigh ------
// K = 256 (16 k-tiles). blockIdx.y selects {W_self -> Ys (+bias)} or
// {W_neigh -> Yn}. BM=128, BK=16, BN=128 or 64. 8 warps = 2(m) x 4(n).

__device__ __forceinline__ float f2tf32(float x) {
    unsigned r;
    asm("cvt.rna.tf32.f32 %0, %1;" : "=r"(r) : "f"(x));
    return __uint_as_float(r);
}

#define MMA_TF32(d0, d1, d2, d3, a0, a1, a2, a3, b0, b1)                    \
    asm volatile(                                                           \
        "mma.sync.aligned.m16n8k8.row.col.f32.tf32.tf32.f32 "               \
        "{%0,%1,%2,%3}, {%4,%5,%6,%7}, {%8,%9}, {%0,%1,%2,%3};"             \
        : "+f"(d0), "+f"(d1), "+f"(d2), "+f"(d3)                            \
        : "r"(a0), "r"(a1), "r"(a2), "r"(a3), "r"(b0), "r"(b1))

template<int BN>
__global__ __launch_bounds__(256) void gemm_tc(
    const float* __restrict__ A,
    const float* __restrict__ Wself, const float* __restrict__ Wneigh,
    const float* __restrict__ bias,
    float* __restrict__ Ys, float* __restrict__ Yn,
    int M, int Nout)
{
    constexpr int BM = 128, BK = 16;
    constexpr int APAD = BK + 4;
    constexpr int BPAD = BN + 4;
    constexpr int NT   = BN / 32;
    constexpr int BLD  = (BK * BN) / (4 * 256);
    constexpr int COLS4 = BN / 4;

    __shared__ float As[2][BM][APAD];
    __shared__ float Bs[2][BK][BPAD];

    int tid  = threadIdx.x;
    int wid  = tid >> 5;
    int lane = tid & 31;
    int wm = wid >> 2;
    int wn = wid & 3;
    int lr = lane >> 2;
    int lc = lane & 3;
    int bm = blockIdx.x * BM;

    int tilesPerHalf = Nout / BN;
    int sel = blockIdx.y / tilesPerHalf;           // 0: self, 1: neigh
    int bn  = (blockIdx.y % tilesPerHalf) * BN;
    const float* W = sel ? Wneigh : Wself;
    float* C = sel ? Yn : Ys;

    float acc[4][NT][4];
    #pragma unroll
    for (int mt = 0; mt < 4; mt++)
        #pragma unroll
        for (int nt = 0; nt < NT; nt++)
            #pragma unroll
            for (int r = 0; r < 4; r++) acc[mt][nt][r] = 0.f;

    int aRow[2], aKq[2];
    #pragma unroll
    for (int it = 0; it < 2; it++) {
        int idx = tid + it * 256;
        aRow[it] = idx >> 2;
        aKq[it]  = (idx & 3) * 4;
    }
    int bKrow[BLD], bNq[BLD];
    #pragma unroll
    for (int it = 0; it < BLD; it++) {
        int idx = tid + it * 256;
        bKrow[it] = idx / COLS4;
        bNq[it]   = (idx % COLS4) * 4;
    }

    float4 aR[2], bR[BLD];
    auto loadRegs = [&](int t) {
        int k0 = t * BK;
        #pragma unroll
        for (int it = 0; it < 2; it++) {
            int grow = bm + aRow[it];
            aR[it] = (grow < M)
                ? *(const float4*)(A + (long)grow * F + k0 + aKq[it])
                : make_float4(0.f, 0.f, 0.f, 0.f);
        }
        #pragma unroll
        for (int it = 0; it < BLD; it++)
            bR[it] = *(const float4*)(W + (long)(k0 + bKrow[it]) * Nout + bn + bNq[it]);
    };
    auto storeSmem = [&](int p) {
        #pragma unroll
        for (int it = 0; it < 2; it++) {
            float4 v;
            v.x = f2tf32(aR[it].x); v.y = f2tf32(aR[it].y);
            v.z = f2tf32(aR[it].z); v.w = f2tf32(aR[it].w);
            *(float4*)&As[p][aRow[it]][aKq[it]] = v;
        }
        #pragma unroll
        for (int it = 0; it < BLD; it++) {
            float4 v;
            v.x = f2tf32(bR[it].x); v.y = f2tf32(bR[it].y);
            v.z = f2tf32(bR[it].z); v.w = f2tf32(bR[it].w);
            *(float4*)&Bs[p][bKrow[it]][bNq[it]] = v;
        }
    };

    loadRegs(0);
    storeSmem(0);
    __syncthreads();

    for (int t = 0; t < 16; t++) {
        int p = t & 1;
        if (t < 15) loadRegs(t + 1);
        #pragma unroll
        for (int ks = 0; ks < 2; ks++) {
            int k0 = ks * 8;
            unsigned af[4][4];
            #pragma unroll
            for (int mt = 0; mt < 4; mt++) {
                int rb = wm * 64 + mt * 16 + lr;
                af[mt][0] = __float_as_uint(As[p][rb    ][k0 + lc    ]);
                af[mt][1] = __float_as_uint(As[p][rb + 8][k0 + lc    ]);
                af[mt][2] = __float_as_uint(As[p][rb    ][k0 + lc + 4]);
                af[mt][3] = __float_as_uint(As[p][rb + 8][k0 + lc + 4]);
            }
            unsigned bf[NT][2];
            #pragma unroll
            for (int nt = 0; nt < NT; nt++) {
                int cb = wn * (BN / 4) + nt * 8 + lr;
                bf[nt][0] = __float_as_uint(Bs[p][k0 + lc    ][cb]);
                bf[nt][1] = __float_as_uint(Bs[p][k0 + lc + 4][cb]);
            }
            #pragma unroll
            for (int mt = 0; mt < 4; mt++)
                #pragma unroll
                for (int nt = 0; nt < NT; nt++)
                    MMA_TF32(acc[mt][nt][0], acc[mt][nt][1],
                             acc[mt][nt][2], acc[mt][nt][3],
                             af[mt][0], af[mt][1], af[mt][2], af[mt][3],
                             bf[nt][0], bf[nt][1]);
        }
        if (t < 15) storeSmem(p ^ 1);
        __syncthreads();
    }

    // epilogue: bias only for the self half
    #pragma unroll
    for (int nt = 0; nt < NT; nt++) {
        int gcol = bn + wn * (BN / 4) + nt * 8 + 2 * lc;
        float2 bb = make_float2(0.f, 0.f);
        if (sel == 0) bb = *(const float2*)(bias + gcol);
        #pragma unroll
        for (int mt = 0; mt < 4; mt++) {
            int row0 = bm + wm * 64 + mt * 16 + lr;
            float2 v0, v1;
            v0.x = acc[mt][nt][0] + bb.x;  v0.y = acc[mt][nt][1] + bb.y;
            v1.x = acc[mt][nt][2] + bb.x;  v1.y = acc[mt][nt][3] + bb.y;
            if (row0 < M)     *(float2*)(C + (long)row0 * Nout + gcol) = v0;
            if (row0 + 8 < M) *(float2*)(C + (long)(row0 + 8) * Nout + gcol) = v1;
        }
    }
}

// ---------------- launch ------------------------------------------------------
extern "C" void kernel_launch(void* const* d_in, const int* in_sizes, int n_in,
                              void* d_out, int out_size) {
    const float* x   = (const float*)d_in[0];
    const int*   src = (const int*)d_in[1];
    const int*   dst = (const int*)d_in[2];
    const float* Ws0 = (const float*)d_in[3];
    const float* Wn0 = (const float*)d_in[4];
    const float* b0  = (const float*)d_in[5];
    const float* Ws1 = (const float*)d_in[6];
    const float* Wn1 = (const float*)d_in[7];
    const float* b1  = (const float*)d_in[8];
    const float* Ws2 = (const float*)d_in[9];
    const float* Wn2 = (const float*)d_in[10];
    const float* b2  = (const float*)d_in[11];

    float* out     = (float*)d_out;
    float* h_final = out;                          // [N, 64]  (tuple elem 0)
    float* h2      = out + (long)N_NODES * OUTF;   // [N, 256] (tuple elem 1)

    float* h1;  float* ys;  float* yn;  int* degp;
    cudaGetSymbolAddress((void**)&h1, g_h1);
    cudaGetSymbolAddress((void**)&ys, g_ys);
    cudaGetSymbolAddress((void**)&yn, g_yn);
    cudaGetSymbolAddress((void**)&degp, g_deg);

    // CSR build (same graph reused by all 3 layers)
    cudaMemsetAsync(degp, 0, N_NODES * sizeof(int));
    count_kernel<<<(N_EDGES + 255) / 256, 256>>>(dst);
    scan_kernel<<<1, 1024>>>();
    fill_kernel<<<(N_EDGES + 255) / 256, 256>>>(src, dst);

    dim3 g256((N_NODES + 127) / 128, 4);   // BN=128, Nout=256: 2 tiles x 2 halves
    dim3 g64((N_NODES + 127) / 128, 2);    // BN=64,  Nout=64:  1 tile  x 2 halves

    // layer 0
    gemm_tc<128><<<g256, 256>>>(x, Ws0, Wn0, b0, ys, yn, N_NODES, 256);
    spmm_add_kernel<64, true><<<(N_NODES + 3) / 4, 256>>>(
        (const float4*)yn, (const float4*)ys, (float4*)h1);
    // layer 1 (output doubles as tuple elem 1)
    gemm_tc<128><<<g256, 256>>>(h1, Ws1, Wn1, b1, ys, yn, N_NODES, 256);
    spmm_add_kernel<64, true><<<(N_NODES + 3) / 4, 256>>>(
        (const float4*)yn, (const float4*)ys, (float4*)h2);
    // layer 2 (64-dim aggregation, no relu)
    gemm_tc<64><<<g64, 256>>>(h2, Ws2, Wn2, b2, ys, yn, N_NODES, 64);
    spmm_add_kernel<16, false><<<(N_NODES + 15) / 16, 256>>>(
        (const float4*)yn, (const float4*)ys, (float4*)h_final);
}